// round 7
// baseline (speedup 1.0000x reference)
#include <cuda_runtime.h>
#include <cstdint>

#define N_PIX 2304
#define HEADS 4
#define HD 16
#define CDIM 64
#define BATCH 2
#define BH 8
#define SPL 72            // N_PIX / 32 values per lane (warp-per-row)
#define SPL4 18           // N_PIX / 128 float4 loads per lane

// ---------------- scratch (static device globals; no allocation) -------------
__device__ float g_qkv1[BATCH*3*CDIM*N_PIX];          // after 1x1 conv, [b][ch][p]
__device__ float g_q[BH*N_PIX*HD];                    // [bh][j][d]
__device__ float g_k[BH*N_PIX*HD];
__device__ float g_v[BH*N_PIX*HD];
__device__ float g_logits[(size_t)BH*N_PIX*N_PIX];    // [rowg][col]  (170 MB)
__device__ float g_entrow[BH*N_PIX];                  // per-row entropy
__device__ float g_attnout[BATCH*CDIM*N_PIX];         // [b][c][p]

// monotone float<->uint order mapping (total order on finite floats)
__device__ __forceinline__ unsigned mapf(float f){
    unsigned u = __float_as_uint(f);
    return (u & 0x80000000u) ? ~u : (u | 0x80000000u);
}
__device__ __forceinline__ float unmapf(unsigned u){
    return __uint_as_float((u & 0x80000000u) ? (u & 0x7fffffffu) : ~u);
}

// ---------------- K1: 1x1 conv (x @ Wqkv + bqkv) -----------------------------
__global__ void k_qkv1(const float* __restrict__ x, const float* __restrict__ W,
                       const float* __restrict__ bias){
    int idx = blockIdx.x*blockDim.x + threadIdx.x;   // BATCH * 24 * N_PIX
    int p  = idx % N_PIX;
    int og = (idx / N_PIX) % 24;
    int b  = idx / (N_PIX*24);
    int o0 = og*8;
    const float* xb = x + b*CDIM*N_PIX + p;
    float acc[8];
    #pragma unroll
    for (int k=0;k<8;k++) acc[k] = bias[o0+k];
    #pragma unroll 8
    for (int c=0;c<CDIM;c++){
        float xv = xb[c*N_PIX];
        #pragma unroll
        for (int k=0;k<8;k++) acc[k] += W[(o0+k)*CDIM + c] * xv;
    }
    float* dst = g_qkv1 + b*3*CDIM*N_PIX + o0*N_PIX + p;
    #pragma unroll
    for (int k=0;k<8;k++) dst[k*N_PIX] = acc[k];
}

// ------- K2: 3x3 depthwise (SAME, zero pad, correlation) + head scatter ------
__global__ void k_pos(const float* __restrict__ Wpos, const float* __restrict__ bpos){
    int idx = blockIdx.x*blockDim.x + threadIdx.x;   // BATCH * 192 * N_PIX
    int p  = idx % N_PIX;
    int ch = (idx / N_PIX) % (3*CDIM);
    int b  = idx / (N_PIX*3*CDIM);
    int y = p / 48, xx = p % 48;
    const float* src = g_qkv1 + ((size_t)b*3*CDIM + ch)*N_PIX;
    const float* wp  = Wpos + ch*9;
    float acc = bpos[ch];
    #pragma unroll
    for (int dy=0; dy<3; dy++){
        int yy = y + dy - 1;
        if (yy < 0 || yy >= 48) continue;
        #pragma unroll
        for (int dx=0; dx<3; dx++){
            int xc = xx + dx - 1;
            if (xc < 0 || xc >= 48) continue;
            acc += src[yy*48 + xc] * wp[dy*3 + dx];
        }
    }
    int which = ch / CDIM;
    int cc    = ch % CDIM;
    int head  = cc / HD, d = cc % HD;
    int bh    = b*HEADS + head;
    float* dst = (which==0) ? g_q : (which==1) ? g_k : g_v;
    dst[((size_t)bh*N_PIX + p)*HD + d] = acc;
}

// ------- K3: QK^T logits (stored once) + per-row entropy, 4 rows/warp --------
__global__ __launch_bounds__(256,1) void k_ent(){
    int gw   = (blockIdx.x*blockDim.x + threadIdx.x) >> 5;   // global warp id
    int lane = threadIdx.x & 31;
    int row0g = gw*4;                       // 4 rows per warp, never straddles bh
    int bh   = row0g / N_PIX;
    int row0 = row0g % N_PIX;

    const float* qb = g_q + ((size_t)bh*N_PIX + row0)*HD;
    float qr[4][HD];
    #pragma unroll
    for (int r=0;r<4;r++)
        #pragma unroll
        for (int d=0;d<HD;d++) qr[r][d] = __ldg(qb + r*HD + d);

    const float4* kb = (const float4*)(g_k + (size_t)bh*N_PIX*HD);
    float* L0 = g_logits + (size_t)row0g*N_PIX;

    float mr[4] = {-1e30f,-1e30f,-1e30f,-1e30f};
    // pass A: logits + row max
    #pragma unroll 4
    for (int s=0; s<SPL; s++){
        int j = s*32 + lane;
        float4 k0 = __ldg(kb + j*4 + 0);
        float4 k1 = __ldg(kb + j*4 + 1);
        float4 k2 = __ldg(kb + j*4 + 2);
        float4 k3 = __ldg(kb + j*4 + 3);
        #pragma unroll
        for (int r=0;r<4;r++){
            float a = qr[r][0]*k0.x + qr[r][1]*k0.y + qr[r][2]*k0.z + qr[r][3]*k0.w;
            float b2= qr[r][4]*k1.x + qr[r][5]*k1.y + qr[r][6]*k1.z + qr[r][7]*k1.w;
            float c = qr[r][8]*k2.x + qr[r][9]*k2.y + qr[r][10]*k2.z+ qr[r][11]*k2.w;
            float d = qr[r][12]*k3.x+ qr[r][13]*k3.y+ qr[r][14]*k3.z+ qr[r][15]*k3.w;
            float l = (a+b2+c+d) * 0.25f;
            L0[(size_t)r*N_PIX + j] = l;
            mr[r] = fmaxf(mr[r], l);
        }
    }
    #pragma unroll
    for (int off=16; off; off>>=1)
        #pragma unroll
        for (int r=0;r<4;r++) mr[r] = fmaxf(mr[r], __shfl_xor_sync(0xffffffffu, mr[r], off));

    // pass B: reload logits via float4 (L2-hot), S and T with final max
    float S[4]={0,0,0,0}, T[4]={0,0,0,0};
    #pragma unroll 2
    for (int s4=0; s4<SPL4; s4++){
        #pragma unroll
        for (int r=0;r<4;r++){
            float4 l4 = __ldg((const float4*)(L0 + (size_t)r*N_PIX) + s4*32 + lane);
            float d0 = l4.x - mr[r]; float e0 = __expf(d0);
            float d1 = l4.y - mr[r]; float e1 = __expf(d1);
            float d2 = l4.z - mr[r]; float e2 = __expf(d2);
            float d3 = l4.w - mr[r]; float e3 = __expf(d3);
            S[r] += (e0+e1)+(e2+e3);
            T[r] += (d0*e0+d1*e1)+(d2*e2+d3*e3);
        }
    }
    #pragma unroll
    for (int off=16; off; off>>=1)
        #pragma unroll
        for (int r=0;r<4;r++){
            S[r] += __shfl_xor_sync(0xffffffffu, S[r], off);
            T[r] += __shfl_xor_sync(0xffffffffu, T[r], off);
        }
    if (lane < 4){
        float Sv = S[0], Tv = T[0];
        #pragma unroll
        for (int r=1;r<4;r++){ Sv = (lane==r)?S[r]:Sv; Tv = (lane==r)?T[r]:Tv; }
        g_entrow[row0g + lane] = logf(Sv) - Tv/Sv;
    }
}

// -------- K4: fused gate + exact kth threshold + sparse softmax * V ----------
// 128 threads = 4 warps, warp-per-row; all 4 rows share one bh.
// Warp 0 recomputes keep[bh] (same reduction order as the old k_gate kernel).
__global__ __launch_bounds__(128,3) void k_sel(
        const float* __restrict__ Wg1, const float* __restrict__ bg1,
        const float* __restrict__ Wg2, const float* __restrict__ bg2){
    __shared__ unsigned candbuf[4][64];
    __shared__ int s_keep;
    int lane = threadIdx.x & 31;
    int wip  = threadIdx.x >> 5;
    int gw   = blockIdx.x*4 + wip;                   // global row id
    int bh   = gw / N_PIX;
    int row  = gw % N_PIX;
    int b = bh >> 2, h = bh & 3;

    // ---- fused gate (warp 0), overlapped with F loads by other warps -------
    if (wip == 0){
        const float* er = g_entrow + bh*N_PIX;
        float s = 0.f;
        #pragma unroll
        for (int i=0;i<SPL;i++) s += er[i*32 + lane];
        #pragma unroll
        for (int off=16; off; off>>=1) s += __shfl_xor_sync(0xffffffffu, s, off);
        if (lane == 0){
            float e = s / (float)N_PIX;
            float dot = bg2[0];
            #pragma unroll
            for (int j=0;j<16;j++){
                float hg = fmaxf(0.f, e*Wg1[j] + bg1[j]);
                dot += hg * Wg2[j];
            }
            float ratio = 1.f/(1.f + expf(-dot)) * 0.9f + 0.1f;
            int kp = (int)ceilf(ratio * (float)N_PIX);
            s_keep = min(max(kp, 1), N_PIX);
        }
    }

    // ---- load row logits as float4 (element j = s4*128 + lane*4 + e) -------
    const float4* L4 = (const float4*)(g_logits + (size_t)gw*N_PIX);
    float F[SPL];
    float fmx = -1e30f, fmn = 1e30f;
    #pragma unroll
    for (int s4=0; s4<SPL4; s4++){
        float4 t = __ldg(L4 + s4*32 + lane);
        F[s4*4+0]=t.x; F[s4*4+1]=t.y; F[s4*4+2]=t.z; F[s4*4+3]=t.w;
        fmx = fmaxf(fmaxf(fmaxf(fmx,t.x),fmaxf(t.y,t.z)),t.w);
        fmn = fminf(fminf(fminf(fmn,t.x),fminf(t.y,t.z)),t.w);
    }
    #pragma unroll
    for (int off=16; off; off>>=1){
        fmx = fmaxf(fmx, __shfl_xor_sync(0xffffffffu, fmx, off));
        fmn = fminf(fmn, __shfl_xor_sync(0xffffffffu, fmn, off));
    }
    __syncthreads();
    int keep = s_keep;

    float fth;
    if (keep >= N_PIX){
        fth = fmn;
    } else {
        unsigned lo = mapf(fmn), hi = mapf(fmx);
        int cnt_lo  = N_PIX;   // count(>= lo)
        int cnt_hi1 = 0;       // count(>= hi+1)
        bool pinned = false;

        // phase 1: full-count bisection while candidate set is large
        while (lo < hi && (cnt_lo - cnt_hi1) > 64){
            unsigned mid = lo + ((hi - lo + 1u) >> 1);
            float fmid = unmapf(mid);
            float c0=0.f,c1=0.f,c2=0.f,c3=0.f;
            #pragma unroll
            for (int s=0; s<SPL; s+=4){
                c0 += (F[s]   >= fmid) ? 1.f : 0.f;
                c1 += (F[s+1] >= fmid) ? 1.f : 0.f;
                c2 += (F[s+2] >= fmid) ? 1.f : 0.f;
                c3 += (F[s+3] >= fmid) ? 1.f : 0.f;
            }
            int cnt = __reduce_add_sync(0xffffffffu, (int)((c0+c1)+(c2+c3)));
            if (cnt == keep){
                float mn = 1e30f;
                #pragma unroll
                for (int s=0; s<SPL; s++)
                    if (F[s] >= fmid) mn = fminf(mn, F[s]);
                #pragma unroll
                for (int off=16; off; off>>=1)
                    mn = fminf(mn, __shfl_xor_sync(0xffffffffu, mn, off));
                lo = mapf(mn);
                pinned = true;
                break;
            }
            if (cnt > keep){ lo = mid; cnt_lo = cnt; }
            else           { hi = mid - 1u; cnt_hi1 = cnt; }
        }

        // phase 2: compact candidates in [lo, hi] and finish on registers
        if (!pinned && lo < hi){
            float flo = unmapf(lo), fhi = unmapf(hi);
            int base = cnt_hi1;                 // count(> hi), fixed
            unsigned* buf = candbuf[wip];
            int nc = 0;
            #pragma unroll
            for (int s=0; s<SPL; s++){
                bool p = (F[s] >= flo) && (F[s] <= fhi);
                unsigned bal = __ballot_sync(0xffffffffu, p);
                if (p){
                    int pos = nc + __popc(bal & ((1u << lane) - 1u));
                    buf[pos] = __float_as_uint(F[s]);
                }
                nc += __popc(bal);
            }
            __syncwarp();
            const float NEG = __int_as_float(0xff800000);   // -inf sentinel
            float cA = (lane      < nc) ? __uint_as_float(buf[lane])      : NEG;
            float cB = (lane + 32 < nc) ? __uint_as_float(buf[lane + 32]) : NEG;
            while (lo < hi){
                unsigned mid = lo + ((hi - lo + 1u) >> 1);
                float fmid = unmapf(mid);
                int c = (cA >= fmid) + (cB >= fmid);
                int cnt = base + __reduce_add_sync(0xffffffffu, c);
                if (cnt >= keep) lo = mid; else hi = mid - 1u;
            }
        }
        fth = unmapf(lo);      // exact kth-largest logit
    }
    float m = fmx;

    // ---- branch-free sparse softmax * V ------------------------------------
    float acc[HD];
    #pragma unroll
    for (int d=0; d<HD; d++) acc[d] = 0.f;
    float S = 0.f;
    const float4* vb = (const float4*)(g_v + (size_t)bh*N_PIX*HD);
    #pragma unroll 2
    for (int s4=0; s4<SPL4; s4++){
        #pragma unroll
        for (int e=0; e<4; e++){
            float f = F[s4*4+e];
            float w = __expf(f - m);
            w = (f >= fth) ? w : 0.f;
            S += w;
            int j = s4*128 + lane*4 + e;
            float4 v0 = __ldg(vb + j*4 + 0);
            float4 v1 = __ldg(vb + j*4 + 1);
            float4 v2 = __ldg(vb + j*4 + 2);
            float4 v3 = __ldg(vb + j*4 + 3);
            acc[0]+=w*v0.x; acc[1]+=w*v0.y; acc[2]+=w*v0.z; acc[3]+=w*v0.w;
            acc[4]+=w*v1.x; acc[5]+=w*v1.y; acc[6]+=w*v1.z; acc[7]+=w*v1.w;
            acc[8]+=w*v2.x; acc[9]+=w*v2.y; acc[10]+=w*v2.z;acc[11]+=w*v2.w;
            acc[12]+=w*v3.x;acc[13]+=w*v3.y;acc[14]+=w*v3.z;acc[15]+=w*v3.w;
        }
    }
    #pragma unroll
    for (int off=16; off; off>>=1){
        S += __shfl_xor_sync(0xffffffffu, S, off);
        #pragma unroll
        for (int d=0; d<HD; d++) acc[d] += __shfl_xor_sync(0xffffffffu, acc[d], off);
    }
    if (lane < HD){
        float v = acc[0];
        #pragma unroll
        for (int d=1; d<HD; d++) v = (lane==d) ? acc[d] : v;
        float inv = 1.f / S;
        g_attnout[((size_t)b*CDIM + h*HD + lane)*N_PIX + row] = v * inv;
    }
}

// ---------------- K5: output projection --------------------------------------
__global__ void k_proj(const float* __restrict__ Wp, const float* __restrict__ bp,
                       float* __restrict__ out){
    int idx = blockIdx.x*blockDim.x + threadIdx.x;   // BATCH * 8 * N_PIX
    int p  = idx % N_PIX;
    int og = (idx / N_PIX) & 7;
    int b  = idx / (N_PIX*8);
    int o0 = og*8;
    const float* a = g_attnout + (size_t)b*CDIM*N_PIX + p;
    float acc[8];
    #pragma unroll
    for (int k=0;k<8;k++) acc[k] = bp[o0+k];
    #pragma unroll 8
    for (int c=0;c<CDIM;c++){
        float av = a[c*N_PIX];
        #pragma unroll
        for (int k=0;k<8;k++) acc[k] += Wp[(o0+k)*CDIM + c] * av;
    }
    float* dst = out + (size_t)b*CDIM*N_PIX + o0*N_PIX + p;
    #pragma unroll
    for (int k=0;k<8;k++) dst[k*N_PIX] = acc[k];
}

// ---------------- launch ------------------------------------------------------
extern "C" void kernel_launch(void* const* d_in, const int* in_sizes, int n_in,
                              void* d_out, int out_size){
    const float* x     = (const float*)d_in[0];
    const float* Wqkv  = (const float*)d_in[1];
    const float* bqkv  = (const float*)d_in[2];
    const float* Wpos  = (const float*)d_in[3];
    const float* bpos  = (const float*)d_in[4];
    const float* Wg1   = (const float*)d_in[5];
    const float* bg1   = (const float*)d_in[6];
    const float* Wg2   = (const float*)d_in[7];
    const float* bg2   = (const float*)d_in[8];
    const float* Wproj = (const float*)d_in[9];
    const float* bproj = (const float*)d_in[10];

    k_qkv1<<<432, 256>>>(x, Wqkv, bqkv);
    k_pos<<<3456, 256>>>(Wpos, bpos);
    k_ent<<<576, 256>>>();                       // 4608 warps x 4 rows
    k_sel<<<4608, 128>>>(Wg1, bg1, Wg2, bg2);    // 4 rows per block, fused gate
    k_proj<<<144, 256>>>(Wproj, bproj, (float*)d_out);
}

// round 9
// speedup vs baseline: 2.7190x; 2.7190x over previous
#include <cuda_runtime.h>
#include <cstdint>

#define N_PIX 2304
#define HEADS 4
#define HD 16
#define CDIM 64
#define BATCH 2
#define BH 8
#define SPL 72            // N_PIX / 32 values per lane (warp-per-row)
#define SPL4 18           // N_PIX / 128 float4 loads per lane

// ---------------- scratch (static device globals; no allocation) -------------
__device__ float g_qkv1[BATCH*3*CDIM*N_PIX];          // after 1x1 conv, [b][ch][p]
__device__ float g_q[BH*N_PIX*HD];                    // [bh][j][d]
__device__ float g_k[BH*N_PIX*HD];
__device__ float g_v[BH*N_PIX*HD];
__device__ float g_logits[(size_t)BH*N_PIX*N_PIX];    // [rowg][col]  (170 MB)
__device__ float g_entrow[BH*N_PIX];                  // per-row entropy
__device__ float g_attnout[BATCH*CDIM*N_PIX];         // [b][c][p]

// monotone float<->uint order mapping (total order on finite floats)
__device__ __forceinline__ unsigned mapf(float f){
    unsigned u = __float_as_uint(f);
    return (u & 0x80000000u) ? ~u : (u | 0x80000000u);
}
__device__ __forceinline__ float unmapf(unsigned u){
    return __uint_as_float((u & 0x80000000u) ? (u & 0x7fffffffu) : ~u);
}

// ---------------- K1: 1x1 conv (x @ Wqkv + bqkv) -----------------------------
__global__ void k_qkv1(const float* __restrict__ x, const float* __restrict__ W,
                       const float* __restrict__ bias){
    int idx = blockIdx.x*blockDim.x + threadIdx.x;   // BATCH * 24 * N_PIX
    int p  = idx % N_PIX;
    int og = (idx / N_PIX) % 24;
    int b  = idx / (N_PIX*24);
    int o0 = og*8;
    const float* xb = x + b*CDIM*N_PIX + p;
    float acc[8];
    #pragma unroll
    for (int k=0;k<8;k++) acc[k] = bias[o0+k];
    #pragma unroll 8
    for (int c=0;c<CDIM;c++){
        float xv = xb[c*N_PIX];
        #pragma unroll
        for (int k=0;k<8;k++) acc[k] += W[(o0+k)*CDIM + c] * xv;
    }
    float* dst = g_qkv1 + b*3*CDIM*N_PIX + o0*N_PIX + p;
    #pragma unroll
    for (int k=0;k<8;k++) dst[k*N_PIX] = acc[k];
}

// ------- K2: 3x3 depthwise (SAME, zero pad, correlation) + head scatter ------
__global__ void k_pos(const float* __restrict__ Wpos, const float* __restrict__ bpos){
    int idx = blockIdx.x*blockDim.x + threadIdx.x;   // BATCH * 192 * N_PIX
    int p  = idx % N_PIX;
    int ch = (idx / N_PIX) % (3*CDIM);
    int b  = idx / (N_PIX*3*CDIM);
    int y = p / 48, xx = p % 48;
    const float* src = g_qkv1 + ((size_t)b*3*CDIM + ch)*N_PIX;
    const float* wp  = Wpos + ch*9;
    float acc = bpos[ch];
    #pragma unroll
    for (int dy=0; dy<3; dy++){
        int yy = y + dy - 1;
        if (yy < 0 || yy >= 48) continue;
        #pragma unroll
        for (int dx=0; dx<3; dx++){
            int xc = xx + dx - 1;
            if (xc < 0 || xc >= 48) continue;
            acc += src[yy*48 + xc] * wp[dy*3 + dx];
        }
    }
    int which = ch / CDIM;
    int cc    = ch % CDIM;
    int head  = cc / HD, d = cc % HD;
    int bh    = b*HEADS + head;
    float* dst = (which==0) ? g_q : (which==1) ? g_k : g_v;
    dst[((size_t)bh*N_PIX + p)*HD + d] = acc;
}

// ------- K3: QK^T logits (stored once) + per-row entropy, 4 rows/warp --------
__global__ __launch_bounds__(256,1) void k_ent(){
    int gw   = (blockIdx.x*blockDim.x + threadIdx.x) >> 5;   // global warp id
    int lane = threadIdx.x & 31;
    int row0g = gw*4;                       // 4 rows per warp, never straddles bh
    int bh   = row0g / N_PIX;
    int row0 = row0g % N_PIX;

    const float* qb = g_q + ((size_t)bh*N_PIX + row0)*HD;
    float qr[4][HD];
    #pragma unroll
    for (int r=0;r<4;r++)
        #pragma unroll
        for (int d=0;d<HD;d++) qr[r][d] = __ldg(qb + r*HD + d);

    const float4* kb = (const float4*)(g_k + (size_t)bh*N_PIX*HD);
    float* L0 = g_logits + (size_t)row0g*N_PIX;

    float mr[4] = {-1e30f,-1e30f,-1e30f,-1e30f};
    // pass A: logits + row max
    #pragma unroll 4
    for (int s=0; s<SPL; s++){
        int j = s*32 + lane;
        float4 k0 = __ldg(kb + j*4 + 0);
        float4 k1 = __ldg(kb + j*4 + 1);
        float4 k2 = __ldg(kb + j*4 + 2);
        float4 k3 = __ldg(kb + j*4 + 3);
        #pragma unroll
        for (int r=0;r<4;r++){
            float a = qr[r][0]*k0.x + qr[r][1]*k0.y + qr[r][2]*k0.z + qr[r][3]*k0.w;
            float b2= qr[r][4]*k1.x + qr[r][5]*k1.y + qr[r][6]*k1.z + qr[r][7]*k1.w;
            float c = qr[r][8]*k2.x + qr[r][9]*k2.y + qr[r][10]*k2.z+ qr[r][11]*k2.w;
            float d = qr[r][12]*k3.x+ qr[r][13]*k3.y+ qr[r][14]*k3.z+ qr[r][15]*k3.w;
            float l = (a+b2+c+d) * 0.25f;
            L0[(size_t)r*N_PIX + j] = l;
            mr[r] = fmaxf(mr[r], l);
        }
    }
    #pragma unroll
    for (int off=16; off; off>>=1)
        #pragma unroll
        for (int r=0;r<4;r++) mr[r] = fmaxf(mr[r], __shfl_xor_sync(0xffffffffu, mr[r], off));

    // pass B: reload logits via float4 (L2-hot), S and T with final max
    float S[4]={0,0,0,0}, T[4]={0,0,0,0};
    #pragma unroll 2
    for (int s4=0; s4<SPL4; s4++){
        #pragma unroll
        for (int r=0;r<4;r++){
            float4 l4 = __ldg((const float4*)(L0 + (size_t)r*N_PIX) + s4*32 + lane);
            float d0 = l4.x - mr[r]; float e0 = __expf(d0);
            float d1 = l4.y - mr[r]; float e1 = __expf(d1);
            float d2 = l4.z - mr[r]; float e2 = __expf(d2);
            float d3 = l4.w - mr[r]; float e3 = __expf(d3);
            S[r] += (e0+e1)+(e2+e3);
            T[r] += (d0*e0+d1*e1)+(d2*e2+d3*e3);
        }
    }
    #pragma unroll
    for (int off=16; off; off>>=1)
        #pragma unroll
        for (int r=0;r<4;r++){
            S[r] += __shfl_xor_sync(0xffffffffu, S[r], off);
            T[r] += __shfl_xor_sync(0xffffffffu, T[r], off);
        }
    if (lane < 4){
        float Sv = S[0], Tv = T[0];
        #pragma unroll
        for (int r=1;r<4;r++){ Sv = (lane==r)?S[r]:Sv; Tv = (lane==r)?T[r]:Tv; }
        g_entrow[row0g + lane] = logf(Sv) - Tv/Sv;
    }
}

// -------- K4: fused gate + exact kth threshold + cooperative P*V GEMM --------
// 128 threads = 4 warps; warp-per-row for the search, then the 4 rows'
// sparse-softmax weights go to smem and the block does a coalesced
// [4 x 2304] * [2304 x 16] GEMM against V (each V line loaded once).
__global__ __launch_bounds__(128,3) void k_sel(
        const float* __restrict__ Wg1, const float* __restrict__ bg1,
        const float* __restrict__ Wg2, const float* __restrict__ bg2){
    __shared__ __align__(16) float ws[4][N_PIX];     // weights, 36.9 KB
    __shared__ float part[4][4][16];                 // [srcwarp][row][d]
    __shared__ float invSs[4];
    __shared__ unsigned candbuf[4][64];
    __shared__ int s_keep;
    int lane = threadIdx.x & 31;
    int wip  = threadIdx.x >> 5;
    int gw   = blockIdx.x*4 + wip;                   // global row id
    int bh   = gw / N_PIX;                           // same for all 4 warps
    int row  = gw % N_PIX;
    int b = bh >> 2, h = bh & 3;

    // ---- fused gate (warp 0) -----------------------------------------------
    if (wip == 0){
        const float* er = g_entrow + bh*N_PIX;
        float s = 0.f;
        #pragma unroll
        for (int i=0;i<SPL;i++) s += er[i*32 + lane];
        #pragma unroll
        for (int off=16; off; off>>=1) s += __shfl_xor_sync(0xffffffffu, s, off);
        if (lane == 0){
            float e = s / (float)N_PIX;
            float dot = bg2[0];
            #pragma unroll
            for (int j=0;j<16;j++){
                float hg = fmaxf(0.f, e*Wg1[j] + bg1[j]);
                dot += hg * Wg2[j];
            }
            float ratio = 1.f/(1.f + expf(-dot)) * 0.9f + 0.1f;
            int kp = (int)ceilf(ratio * (float)N_PIX);
            s_keep = min(max(kp, 1), N_PIX);
        }
    }

    // ---- load row logits as float4 (element j = s4*128 + lane*4 + e) -------
    const float4* L4 = (const float4*)(g_logits + (size_t)gw*N_PIX);
    float F[SPL];
    float fmx = -1e30f, fmn = 1e30f;
    #pragma unroll
    for (int s4=0; s4<SPL4; s4++){
        float4 t = __ldg(L4 + s4*32 + lane);
        F[s4*4+0]=t.x; F[s4*4+1]=t.y; F[s4*4+2]=t.z; F[s4*4+3]=t.w;
        fmx = fmaxf(fmaxf(fmaxf(fmx,t.x),fmaxf(t.y,t.z)),t.w);
        fmn = fminf(fminf(fminf(fmn,t.x),fminf(t.y,t.z)),t.w);
    }
    #pragma unroll
    for (int off=16; off; off>>=1){
        fmx = fmaxf(fmx, __shfl_xor_sync(0xffffffffu, fmx, off));
        fmn = fminf(fmn, __shfl_xor_sync(0xffffffffu, fmn, off));
    }
    __syncthreads();
    int keep = s_keep;

    float fth;
    if (keep >= N_PIX){
        fth = fmn;
    } else {
        unsigned lo = mapf(fmn), hi = mapf(fmx);
        int cnt_lo  = N_PIX;   // count(>= lo)
        int cnt_hi1 = 0;       // count(>= hi+1)
        bool pinned = false;

        // phase 1: full-count bisection while candidate set is large
        while (lo < hi && (cnt_lo - cnt_hi1) > 64){
            unsigned mid = lo + ((hi - lo + 1u) >> 1);
            float fmid = unmapf(mid);
            float c0=0.f,c1=0.f,c2=0.f,c3=0.f;
            #pragma unroll
            for (int s=0; s<SPL; s+=4){
                c0 += (F[s]   >= fmid) ? 1.f : 0.f;
                c1 += (F[s+1] >= fmid) ? 1.f : 0.f;
                c2 += (F[s+2] >= fmid) ? 1.f : 0.f;
                c3 += (F[s+3] >= fmid) ? 1.f : 0.f;
            }
            int cnt = __reduce_add_sync(0xffffffffu, (int)((c0+c1)+(c2+c3)));
            if (cnt == keep){
                float mn = 1e30f;
                #pragma unroll
                for (int s=0; s<SPL; s++)
                    if (F[s] >= fmid) mn = fminf(mn, F[s]);
                #pragma unroll
                for (int off=16; off; off>>=1)
                    mn = fminf(mn, __shfl_xor_sync(0xffffffffu, mn, off));
                lo = mapf(mn);
                pinned = true;
                break;
            }
            if (cnt > keep){ lo = mid; cnt_lo = cnt; }
            else           { hi = mid - 1u; cnt_hi1 = cnt; }
        }

        // phase 2: compact candidates in [lo, hi] and finish on registers
        if (!pinned && lo < hi){
            float flo = unmapf(lo), fhi = unmapf(hi);
            int base = cnt_hi1;                 // count(> hi), fixed
            unsigned* buf = candbuf[wip];
            int nc = 0;
            #pragma unroll
            for (int s=0; s<SPL; s++){
                bool p = (F[s] >= flo) && (F[s] <= fhi);
                unsigned bal = __ballot_sync(0xffffffffu, p);
                if (p){
                    int pos = nc + __popc(bal & ((1u << lane) - 1u));
                    buf[pos] = __float_as_uint(F[s]);
                }
                nc += __popc(bal);
            }
            __syncwarp();
            const float NEG = __int_as_float(0xff800000);   // -inf sentinel
            float cA = (lane      < nc) ? __uint_as_float(buf[lane])      : NEG;
            float cB = (lane + 32 < nc) ? __uint_as_float(buf[lane + 32]) : NEG;
            while (lo < hi){
                unsigned mid = lo + ((hi - lo + 1u) >> 1);
                float fmid = unmapf(mid);
                int c = (cA >= fmid) + (cB >= fmid);
                int cnt = base + __reduce_add_sync(0xffffffffu, c);
                if (cnt >= keep) lo = mid; else hi = mid - 1u;
            }
        }
        fth = unmapf(lo);      // exact kth-largest logit
    }
    float m = fmx;

    // ---- weights -> smem, S -> invSs ---------------------------------------
    float S = 0.f;
    #pragma unroll
    for (int s4=0; s4<SPL4; s4++){
        float f0=F[s4*4+0], f1=F[s4*4+1], f2=F[s4*4+2], f3=F[s4*4+3];
        float w0=__expf(f0-m); w0 = (f0>=fth)?w0:0.f;
        float w1=__expf(f1-m); w1 = (f1>=fth)?w1:0.f;
        float w2=__expf(f2-m); w2 = (f2>=fth)?w2:0.f;
        float w3=__expf(f3-m); w3 = (f3>=fth)?w3:0.f;
        S += (w0+w1)+(w2+w3);
        *((float4*)&ws[wip][s4*128 + lane*4]) = make_float4(w0,w1,w2,w3);
    }
    #pragma unroll
    for (int off=16; off; off>>=1) S += __shfl_xor_sync(0xffffffffu, S, off);
    if (lane == 0) invSs[wip] = 1.f / S;
    __syncthreads();

    // ---- cooperative GEMM: out[4][16] = ws[4][2304] * V[2304][16] -----------
    // warp wip owns j-strip [wip*576, wip*576+576); 8 consecutive j per LDG.128
    // round (512B contiguous), each V line loaded once per block.
    {
        int dg = lane & 3;          // d-component group (4 floats)
        int jo = lane >> 2;         // 0..7 consecutive j offset
        const float4* vrow = (const float4*)(g_v + (size_t)bh*N_PIX*HD);
        float4 a0 = {0,0,0,0}, a1 = {0,0,0,0}, a2 = {0,0,0,0}, a3 = {0,0,0,0};
        int jb = wip*576 + jo;
        #pragma unroll 4
        for (int it=0; it<72; it++){
            int j = jb + it*8;
            float4 v = vrow[j*4 + dg];
            float w0 = ws[0][j], w1 = ws[1][j], w2 = ws[2][j], w3 = ws[3][j];
            a0.x += w0*v.x; a0.y += w0*v.y; a0.z += w0*v.z; a0.w += w0*v.w;
            a1.x += w1*v.x; a1.y += w1*v.y; a1.z += w1*v.z; a1.w += w1*v.w;
            a2.x += w2*v.x; a2.y += w2*v.y; a2.z += w2*v.z; a2.w += w2*v.w;
            a3.x += w3*v.x; a3.y += w3*v.y; a3.z += w3*v.z; a3.w += w3*v.w;
        }
        // reduce across jo (lanes differing in bits 2..4)
        #pragma unroll
        for (int off=4; off<32; off<<=1){
            a0.x += __shfl_xor_sync(0xffffffffu, a0.x, off);
            a0.y += __shfl_xor_sync(0xffffffffu, a0.y, off);
            a0.z += __shfl_xor_sync(0xffffffffu, a0.z, off);
            a0.w += __shfl_xor_sync(0xffffffffu, a0.w, off);
            a1.x += __shfl_xor_sync(0xffffffffu, a1.x, off);
            a1.y += __shfl_xor_sync(0xffffffffu, a1.y, off);
            a1.z += __shfl_xor_sync(0xffffffffu, a1.z, off);
            a1.w += __shfl_xor_sync(0xffffffffu, a1.w, off);
            a2.x += __shfl_xor_sync(0xffffffffu, a2.x, off);
            a2.y += __shfl_xor_sync(0xffffffffu, a2.y, off);
            a2.z += __shfl_xor_sync(0xffffffffu, a2.z, off);
            a2.w += __shfl_xor_sync(0xffffffffu, a2.w, off);
            a3.x += __shfl_xor_sync(0xffffffffu, a3.x, off);
            a3.y += __shfl_xor_sync(0xffffffffu, a3.y, off);
            a3.z += __shfl_xor_sync(0xffffffffu, a3.z, off);
            a3.w += __shfl_xor_sync(0xffffffffu, a3.w, off);
        }
        if (lane < 4){
            ((float4*)part[wip][0])[lane==0?0:0] = a0;  // placeholder avoided below
        }
        // store partials: lane dg<4 && jo==0 -> lanes 0..3 hold d-groups 0..3
        if (lane < 4){
            ((float4*)&part[wip][0][lane*4])[0] = a0;
            ((float4*)&part[wip][1][lane*4])[0] = a1;
            ((float4*)&part[wip][2][lane*4])[0] = a2;
            ((float4*)&part[wip][3][lane*4])[0] = a3;
        }
    }
    __syncthreads();

    // ---- final: warp r sums srcwarp partials, scales, stores ---------------
    if (lane < 16){
        float s = part[0][wip][lane] + part[1][wip][lane]
                + part[2][wip][lane] + part[3][wip][lane];
        float o = s * invSs[wip];
        g_attnout[((size_t)b*CDIM + h*HD + lane)*N_PIX + row] = o;
    }
}

// ---------------- K5: output projection --------------------------------------
__global__ void k_proj(const float* __restrict__ Wp, const float* __restrict__ bp,
                       float* __restrict__ out){
    int idx = blockIdx.x*blockDim.x + threadIdx.x;   // BATCH * 8 * N_PIX
    int p  = idx % N_PIX;
    int og = (idx / N_PIX) & 7;
    int b  = idx / (N_PIX*8);
    int o0 = og*8;
    const float* a = g_attnout + (size_t)b*CDIM*N_PIX + p;
    float acc[8];
    #pragma unroll
    for (int k=0;k<8;k++) acc[k] = bp[o0+k];
    #pragma unroll 8
    for (int c=0;c<CDIM;c++){
        float av = a[c*N_PIX];
        #pragma unroll
        for (int k=0;k<8;k++) acc[k] += Wp[(o0+k)*CDIM + c] * av;
    }
    float* dst = out + (size_t)b*CDIM*N_PIX + o0*N_PIX + p;
    #pragma unroll
    for (int k=0;k<8;k++) dst[k*N_PIX] = acc[k];
}

// ---------------- launch ------------------------------------------------------
extern "C" void kernel_launch(void* const* d_in, const int* in_sizes, int n_in,
                              void* d_out, int out_size){
    const float* x     = (const float*)d_in[0];
    const float* Wqkv  = (const float*)d_in[1];
    const float* bqkv  = (const float*)d_in[2];
    const float* Wpos  = (const float*)d_in[3];
    const float* bpos  = (const float*)d_in[4];
    const float* Wg1   = (const float*)d_in[5];
    const float* bg1   = (const float*)d_in[6];
    const float* Wg2   = (const float*)d_in[7];
    const float* bg2   = (const float*)d_in[8];
    const float* Wproj = (const float*)d_in[9];
    const float* bproj = (const float*)d_in[10];

    k_qkv1<<<432, 256>>>(x, Wqkv, bqkv);
    k_pos<<<3456, 256>>>(Wpos, bpos);
    k_ent<<<576, 256>>>();                       // 4608 warps x 4 rows
    k_sel<<<4608, 128>>>(Wg1, bg1, Wg2, bg2);    // 4 rows per block, fused gate
    k_proj<<<144, 256>>>(Wproj, bproj, (float*)d_out);
}

// round 10
// speedup vs baseline: 2.8448x; 1.0463x over previous
#include <cuda_runtime.h>
#include <cstdint>

#define N_PIX 2304
#define HEADS 4
#define HD 16
#define CDIM 64
#define BATCH 2
#define BH 8
#define SPL 72            // N_PIX / 32 values per lane (warp-per-row)
#define SPL4 18           // N_PIX / 128 float4 loads per lane

// ---------------- scratch (static device globals; no allocation) -------------
__device__ float g_qkv1[BATCH*3*CDIM*N_PIX];          // after 1x1 conv, [b][ch][p]
__device__ float g_q[BH*N_PIX*HD];                    // [bh][j][d]
__device__ float g_k[BH*N_PIX*HD];
__device__ float g_v[BH*N_PIX*HD];
__device__ float g_logits[(size_t)BH*N_PIX*N_PIX];    // [rowg][col]  (170 MB)
__device__ float g_entrow[BH*N_PIX];                  // per-row entropy
__device__ float g_attnout[BATCH*CDIM*N_PIX];         // [b][c][p]

// monotone float<->uint order mapping (total order on finite floats)
__device__ __forceinline__ unsigned mapf(float f){
    unsigned u = __float_as_uint(f);
    return (u & 0x80000000u) ? ~u : (u | 0x80000000u);
}
__device__ __forceinline__ float unmapf(unsigned u){
    return __uint_as_float((u & 0x80000000u) ? (u & 0x7fffffffu) : ~u);
}

// ---------------- K1: 1x1 conv (x @ Wqkv + bqkv) -----------------------------
__global__ void k_qkv1(const float* __restrict__ x, const float* __restrict__ W,
                       const float* __restrict__ bias){
    int idx = blockIdx.x*blockDim.x + threadIdx.x;   // BATCH * 24 * N_PIX
    int p  = idx % N_PIX;
    int og = (idx / N_PIX) % 24;
    int b  = idx / (N_PIX*24);
    int o0 = og*8;
    const float* xb = x + b*CDIM*N_PIX + p;
    float acc[8];
    #pragma unroll
    for (int k=0;k<8;k++) acc[k] = bias[o0+k];
    #pragma unroll 8
    for (int c=0;c<CDIM;c++){
        float xv = xb[c*N_PIX];
        #pragma unroll
        for (int k=0;k<8;k++) acc[k] += W[(o0+k)*CDIM + c] * xv;
    }
    float* dst = g_qkv1 + b*3*CDIM*N_PIX + o0*N_PIX + p;
    #pragma unroll
    for (int k=0;k<8;k++) dst[k*N_PIX] = acc[k];
}

// ------- K2: 3x3 depthwise (SAME, zero pad, correlation) + head scatter ------
__global__ void k_pos(const float* __restrict__ Wpos, const float* __restrict__ bpos){
    int idx = blockIdx.x*blockDim.x + threadIdx.x;   // BATCH * 192 * N_PIX
    int p  = idx % N_PIX;
    int ch = (idx / N_PIX) % (3*CDIM);
    int b  = idx / (N_PIX*3*CDIM);
    int y = p / 48, xx = p % 48;
    const float* src = g_qkv1 + ((size_t)b*3*CDIM + ch)*N_PIX;
    const float* wp  = Wpos + ch*9;
    float acc = bpos[ch];
    #pragma unroll
    for (int dy=0; dy<3; dy++){
        int yy = y + dy - 1;
        if (yy < 0 || yy >= 48) continue;
        #pragma unroll
        for (int dx=0; dx<3; dx++){
            int xc = xx + dx - 1;
            if (xc < 0 || xc >= 48) continue;
            acc += src[yy*48 + xc] * wp[dy*3 + dx];
        }
    }
    int which = ch / CDIM;
    int cc    = ch % CDIM;
    int head  = cc / HD, d = cc % HD;
    int bh    = b*HEADS + head;
    float* dst = (which==0) ? g_q : (which==1) ? g_k : g_v;
    dst[((size_t)bh*N_PIX + p)*HD + d] = acc;
}

// ------- K3: QK^T logits (stored once) + per-row entropy, 4 rows/warp --------
// 128-thread blocks, 4 resident blocks/SM -> 16 warps/SM to hide store latency.
__global__ __launch_bounds__(128,4) void k_ent(){
    int gw   = blockIdx.x*4 + (threadIdx.x >> 5);    // global warp id
    int lane = threadIdx.x & 31;
    int row0g = gw*4;                       // 4 rows per warp, never straddles bh
    int bh   = row0g / N_PIX;
    int row0 = row0g % N_PIX;

    const float* qb = g_q + ((size_t)bh*N_PIX + row0)*HD;
    float qr[4][HD];
    #pragma unroll
    for (int r=0;r<4;r++)
        #pragma unroll
        for (int d=0;d<HD;d++) qr[r][d] = __ldg(qb + r*HD + d);

    const float4* kb = (const float4*)(g_k + (size_t)bh*N_PIX*HD);
    float* L0 = g_logits + (size_t)row0g*N_PIX;

    float mr[4] = {-1e30f,-1e30f,-1e30f,-1e30f};
    // pass A: logits + row max
    #pragma unroll 4
    for (int s=0; s<SPL; s++){
        int j = s*32 + lane;
        float4 k0 = __ldg(kb + j*4 + 0);
        float4 k1 = __ldg(kb + j*4 + 1);
        float4 k2 = __ldg(kb + j*4 + 2);
        float4 k3 = __ldg(kb + j*4 + 3);
        #pragma unroll
        for (int r=0;r<4;r++){
            float a = qr[r][0]*k0.x + qr[r][1]*k0.y + qr[r][2]*k0.z + qr[r][3]*k0.w;
            float b2= qr[r][4]*k1.x + qr[r][5]*k1.y + qr[r][6]*k1.z + qr[r][7]*k1.w;
            float c = qr[r][8]*k2.x + qr[r][9]*k2.y + qr[r][10]*k2.z+ qr[r][11]*k2.w;
            float d = qr[r][12]*k3.x+ qr[r][13]*k3.y+ qr[r][14]*k3.z+ qr[r][15]*k3.w;
            float l = (a+b2+c+d) * 0.25f;
            L0[(size_t)r*N_PIX + j] = l;
            mr[r] = fmaxf(mr[r], l);
        }
    }
    #pragma unroll
    for (int off=16; off; off>>=1)
        #pragma unroll
        for (int r=0;r<4;r++) mr[r] = fmaxf(mr[r], __shfl_xor_sync(0xffffffffu, mr[r], off));

    // pass B: reload logits via float4 (L2-hot), S and T with final max
    float S[4]={0,0,0,0}, T[4]={0,0,0,0};
    #pragma unroll 2
    for (int s4=0; s4<SPL4; s4++){
        #pragma unroll
        for (int r=0;r<4;r++){
            float4 l4 = __ldg((const float4*)(L0 + (size_t)r*N_PIX) + s4*32 + lane);
            float d0 = l4.x - mr[r]; float e0 = __expf(d0);
            float d1 = l4.y - mr[r]; float e1 = __expf(d1);
            float d2 = l4.z - mr[r]; float e2 = __expf(d2);
            float d3 = l4.w - mr[r]; float e3 = __expf(d3);
            S[r] += (e0+e1)+(e2+e3);
            T[r] += (d0*e0+d1*e1)+(d2*e2+d3*e3);
        }
    }
    #pragma unroll
    for (int off=16; off; off>>=1)
        #pragma unroll
        for (int r=0;r<4;r++){
            S[r] += __shfl_xor_sync(0xffffffffu, S[r], off);
            T[r] += __shfl_xor_sync(0xffffffffu, T[r], off);
        }
    if (lane < 4){
        float Sv = S[0], Tv = T[0];
        #pragma unroll
        for (int r=1;r<4;r++){ Sv = (lane==r)?S[r]:Sv; Tv = (lane==r)?T[r]:Tv; }
        g_entrow[row0g + lane] = logf(Sv) - Tv/Sv;
    }
}

// -------- K4: fused gate + exact kth threshold + cooperative P*V GEMM --------
__global__ __launch_bounds__(128,4) void k_sel(
        const float* __restrict__ Wg1, const float* __restrict__ bg1,
        const float* __restrict__ Wg2, const float* __restrict__ bg2){
    __shared__ __align__(16) float ws[4][N_PIX];     // weights, 36.9 KB
    __shared__ float part[4][4][16];                 // [srcwarp][row][d]
    __shared__ float invSs[4];
    __shared__ unsigned candbuf[4][64];
    __shared__ int s_keep;
    int lane = threadIdx.x & 31;
    int wip  = threadIdx.x >> 5;
    int gw   = blockIdx.x*4 + wip;                   // global row id
    int bh   = gw / N_PIX;                           // same for all 4 warps
    int row  = gw % N_PIX;
    int b = bh >> 2, h = bh & 3;

    // ---- fused gate (warp 0) -----------------------------------------------
    if (wip == 0){
        const float* er = g_entrow + bh*N_PIX;
        float s = 0.f;
        #pragma unroll
        for (int i=0;i<SPL;i++) s += er[i*32 + lane];
        #pragma unroll
        for (int off=16; off; off>>=1) s += __shfl_xor_sync(0xffffffffu, s, off);
        if (lane == 0){
            float e = s / (float)N_PIX;
            float dot = bg2[0];
            #pragma unroll
            for (int j=0;j<16;j++){
                float hg = fmaxf(0.f, e*Wg1[j] + bg1[j]);
                dot += hg * Wg2[j];
            }
            float ratio = 1.f/(1.f + expf(-dot)) * 0.9f + 0.1f;
            int kp = (int)ceilf(ratio * (float)N_PIX);
            s_keep = min(max(kp, 1), N_PIX);
        }
    }

    // ---- load row logits as float4 (element j = s4*128 + lane*4 + e) -------
    const float4* L4 = (const float4*)(g_logits + (size_t)gw*N_PIX);
    float F[SPL];
    float fmx = -1e30f, fmn = 1e30f;
    #pragma unroll
    for (int s4=0; s4<SPL4; s4++){
        float4 t = __ldg(L4 + s4*32 + lane);
        F[s4*4+0]=t.x; F[s4*4+1]=t.y; F[s4*4+2]=t.z; F[s4*4+3]=t.w;
        fmx = fmaxf(fmaxf(fmaxf(fmx,t.x),fmaxf(t.y,t.z)),t.w);
        fmn = fminf(fminf(fminf(fmn,t.x),fminf(t.y,t.z)),t.w);
    }
    #pragma unroll
    for (int off=16; off; off>>=1){
        fmx = fmaxf(fmx, __shfl_xor_sync(0xffffffffu, fmx, off));
        fmn = fminf(fmn, __shfl_xor_sync(0xffffffffu, fmn, off));
    }
    __syncthreads();
    int keep = s_keep;

    float fth;
    if (keep >= N_PIX){
        fth = fmn;
    } else {
        unsigned lo = mapf(fmn), hi = mapf(fmx);
        int cnt_lo  = N_PIX;   // count(>= lo)
        int cnt_hi1 = 0;       // count(>= hi+1)
        bool pinned = false;

        // phase 1: full-count bisection while candidate set is large
        while (lo < hi && (cnt_lo - cnt_hi1) > 64){
            unsigned mid = lo + ((hi - lo + 1u) >> 1);
            float fmid = unmapf(mid);
            float c0=0.f,c1=0.f,c2=0.f,c3=0.f;
            #pragma unroll
            for (int s=0; s<SPL; s+=4){
                c0 += (F[s]   >= fmid) ? 1.f : 0.f;
                c1 += (F[s+1] >= fmid) ? 1.f : 0.f;
                c2 += (F[s+2] >= fmid) ? 1.f : 0.f;
                c3 += (F[s+3] >= fmid) ? 1.f : 0.f;
            }
            int cnt = __reduce_add_sync(0xffffffffu, (int)((c0+c1)+(c2+c3)));
            if (cnt == keep){
                float mn = 1e30f;
                #pragma unroll
                for (int s=0; s<SPL; s++)
                    if (F[s] >= fmid) mn = fminf(mn, F[s]);
                #pragma unroll
                for (int off=16; off; off>>=1)
                    mn = fminf(mn, __shfl_xor_sync(0xffffffffu, mn, off));
                lo = mapf(mn);
                pinned = true;
                break;
            }
            if (cnt > keep){ lo = mid; cnt_lo = cnt; }
            else           { hi = mid - 1u; cnt_hi1 = cnt; }
        }

        // phase 2: compact candidates in [lo, hi] and finish on registers
        if (!pinned && lo < hi){
            float flo = unmapf(lo), fhi = unmapf(hi);
            int base = cnt_hi1;                 // count(> hi), fixed
            unsigned* buf = candbuf[wip];
            int nc = 0;
            #pragma unroll
            for (int s=0; s<SPL; s++){
                bool p = (F[s] >= flo) && (F[s] <= fhi);
                unsigned bal = __ballot_sync(0xffffffffu, p);
                if (p){
                    int pos = nc + __popc(bal & ((1u << lane) - 1u));
                    buf[pos] = __float_as_uint(F[s]);
                }
                nc += __popc(bal);
            }
            __syncwarp();
            const float NEG = __int_as_float(0xff800000);   // -inf sentinel
            float cA = (lane      < nc) ? __uint_as_float(buf[lane])      : NEG;
            float cB = (lane + 32 < nc) ? __uint_as_float(buf[lane + 32]) : NEG;
            while (lo < hi){
                unsigned mid = lo + ((hi - lo + 1u) >> 1);
                float fmid = unmapf(mid);
                int c = (cA >= fmid) + (cB >= fmid);
                int cnt = base + __reduce_add_sync(0xffffffffu, c);
                if (cnt >= keep) lo = mid; else hi = mid - 1u;
            }
        }
        fth = unmapf(lo);      // exact kth-largest logit
    }
    float m = fmx;

    // ---- weights -> smem, S -> invSs ---------------------------------------
    float S = 0.f;
    #pragma unroll
    for (int s4=0; s4<SPL4; s4++){
        float f0=F[s4*4+0], f1=F[s4*4+1], f2=F[s4*4+2], f3=F[s4*4+3];
        float w0=__expf(f0-m); w0 = (f0>=fth)?w0:0.f;
        float w1=__expf(f1-m); w1 = (f1>=fth)?w1:0.f;
        float w2=__expf(f2-m); w2 = (f2>=fth)?w2:0.f;
        float w3=__expf(f3-m); w3 = (f3>=fth)?w3:0.f;
        S += (w0+w1)+(w2+w3);
        *((float4*)&ws[wip][s4*128 + lane*4]) = make_float4(w0,w1,w2,w3);
    }
    #pragma unroll
    for (int off=16; off; off>>=1) S += __shfl_xor_sync(0xffffffffu, S, off);
    if (lane == 0) invSs[wip] = 1.f / S;
    __syncthreads();

    // ---- cooperative GEMM: out[4][16] = ws[4][2304] * V[2304][16] -----------
    {
        int dg = lane & 3;          // d-component group (4 floats)
        int jo = lane >> 2;         // 0..7 consecutive j offset
        const float4* vrow = (const float4*)(g_v + (size_t)bh*N_PIX*HD);
        float4 a0 = {0,0,0,0}, a1 = {0,0,0,0}, a2 = {0,0,0,0}, a3 = {0,0,0,0};
        int jb = wip*576 + jo;
        #pragma unroll 4
        for (int it=0; it<72; it++){
            int j = jb + it*8;
            float4 v = vrow[j*4 + dg];
            float w0 = ws[0][j], w1 = ws[1][j], w2 = ws[2][j], w3 = ws[3][j];
            a0.x += w0*v.x; a0.y += w0*v.y; a0.z += w0*v.z; a0.w += w0*v.w;
            a1.x += w1*v.x; a1.y += w1*v.y; a1.z += w1*v.z; a1.w += w1*v.w;
            a2.x += w2*v.x; a2.y += w2*v.y; a2.z += w2*v.z; a2.w += w2*v.w;
            a3.x += w3*v.x; a3.y += w3*v.y; a3.z += w3*v.z; a3.w += w3*v.w;
        }
        // reduce across jo (lanes differing in bits 2..4)
        #pragma unroll
        for (int off=4; off<32; off<<=1){
            a0.x += __shfl_xor_sync(0xffffffffu, a0.x, off);
            a0.y += __shfl_xor_sync(0xffffffffu, a0.y, off);
            a0.z += __shfl_xor_sync(0xffffffffu, a0.z, off);
            a0.w += __shfl_xor_sync(0xffffffffu, a0.w, off);
            a1.x += __shfl_xor_sync(0xffffffffu, a1.x, off);
            a1.y += __shfl_xor_sync(0xffffffffu, a1.y, off);
            a1.z += __shfl_xor_sync(0xffffffffu, a1.z, off);
            a1.w += __shfl_xor_sync(0xffffffffu, a1.w, off);
            a2.x += __shfl_xor_sync(0xffffffffu, a2.x, off);
            a2.y += __shfl_xor_sync(0xffffffffu, a2.y, off);
            a2.z += __shfl_xor_sync(0xffffffffu, a2.z, off);
            a2.w += __shfl_xor_sync(0xffffffffu, a2.w, off);
            a3.x += __shfl_xor_sync(0xffffffffu, a3.x, off);
            a3.y += __shfl_xor_sync(0xffffffffu, a3.y, off);
            a3.z += __shfl_xor_sync(0xffffffffu, a3.z, off);
            a3.w += __shfl_xor_sync(0xffffffffu, a3.w, off);
        }
        if (lane < 4){
            ((float4*)&part[wip][0][lane*4])[0] = a0;
            ((float4*)&part[wip][1][lane*4])[0] = a1;
            ((float4*)&part[wip][2][lane*4])[0] = a2;
            ((float4*)&part[wip][3][lane*4])[0] = a3;
        }
    }
    __syncthreads();

    // ---- final: warp r sums srcwarp partials, scales, stores ---------------
    if (lane < 16){
        float s = part[0][wip][lane] + part[1][wip][lane]
                + part[2][wip][lane] + part[3][wip][lane];
        float o = s * invSs[wip];
        g_attnout[((size_t)b*CDIM + h*HD + lane)*N_PIX + row] = o;
    }
}

// ---------------- K5: output projection --------------------------------------
__global__ void k_proj(const float* __restrict__ Wp, const float* __restrict__ bp,
                       float* __restrict__ out){
    int idx = blockIdx.x*blockDim.x + threadIdx.x;   // BATCH * 8 * N_PIX
    int p  = idx % N_PIX;
    int og = (idx / N_PIX) & 7;
    int b  = idx / (N_PIX*8);
    int o0 = og*8;
    const float* a = g_attnout + (size_t)b*CDIM*N_PIX + p;
    float acc[8];
    #pragma unroll
    for (int k=0;k<8;k++) acc[k] = bp[o0+k];
    #pragma unroll 8
    for (int c=0;c<CDIM;c++){
        float av = a[c*N_PIX];
        #pragma unroll
        for (int k=0;k<8;k++) acc[k] += Wp[(o0+k)*CDIM + c] * av;
    }
    float* dst = out + (size_t)b*CDIM*N_PIX + o0*N_PIX + p;
    #pragma unroll
    for (int k=0;k<8;k++) dst[k*N_PIX] = acc[k];
}

// ---------------- launch ------------------------------------------------------
extern "C" void kernel_launch(void* const* d_in, const int* in_sizes, int n_in,
                              void* d_out, int out_size){
    const float* x     = (const float*)d_in[0];
    const float* Wqkv  = (const float*)d_in[1];
    const float* bqkv  = (const float*)d_in[2];
    const float* Wpos  = (const float*)d_in[3];
    const float* bpos  = (const float*)d_in[4];
    const float* Wg1   = (const float*)d_in[5];
    const float* bg1   = (const float*)d_in[6];
    const float* Wg2   = (const float*)d_in[7];
    const float* bg2   = (const float*)d_in[8];
    const float* Wproj = (const float*)d_in[9];
    const float* bproj = (const float*)d_in[10];

    k_qkv1<<<432, 256>>>(x, Wqkv, bqkv);
    k_pos<<<3456, 256>>>(Wpos, bpos);
    k_ent<<<1152, 128>>>();                      // 4608 warps x 4 rows
    k_sel<<<4608, 128>>>(Wg1, bg1, Wg2, bg2);    // 4 rows per block, fused gate
    k_proj<<<144, 256>>>(Wproj, bproj, (float*)d_out);
}